// round 4
// baseline (speedup 1.0000x reference)
#include <cuda_runtime.h>
#include <cuda_bf16.h>

// Problem constants
#define NN 10000
#define EE 128000
#define CC 128
#define AA 10
#define FF 8
#define MSGW 1152
#define OUTR_ELEMS (NN * CC * 9)

// ---------------- scratch (device globals) ---------------------------------
__device__ float g_h[NN * CC];
__device__ float g_tpw[(long)EE * 384];
__device__ float g_msg_r[NN * MSGW];
__device__ float g_msg_i[NN * MSGW];
__device__ int   g_deg[NN];
__device__ int   g_cur[NN];
__device__ int   g_off[NN + 1];
__device__ int   g_elist[EE];
__device__ int   g_slist[EE];

__device__ __forceinline__ float silu(float x) {
    return x * (1.0f / (1.0f + __expf(-x)));
}

// f32x2 packed helpers (sm_100+)
__device__ __forceinline__ unsigned long long pack2(float lo, float hi) {
    unsigned long long r;
    asm("mov.b64 %0, {%1, %2};" : "=l"(r) : "f"(lo), "f"(hi));
    return r;
}
__device__ __forceinline__ void unpack2(unsigned long long v, float& lo, float& hi) {
    asm("mov.b64 {%0, %1}, %2;" : "=f"(lo), "=f"(hi) : "l"(v));
}
__device__ __forceinline__ void ffma2(unsigned long long& acc,
                                      unsigned long long a, unsigned long long b) {
    asm("fma.rn.f32x2 %0, %1, %2, %0;" : "+l"(acc) : "l"(a), "l"(b));
}

// ---------------- CSR build -------------------------------------------------
__global__ void k_reset() {
    int t = blockIdx.x * 256 + threadIdx.x;
    if (t < NN) { g_deg[t] = 0; g_cur[t] = 0; }
}
__global__ void k_count(const int* __restrict__ eidx) {
    int e = blockIdx.x * 256 + threadIdx.x;
    if (e < EE) atomicAdd(&g_deg[eidx[EE + e]], 1);
}
__global__ void k_scan() {  // single block, 1024 threads; NN = 1000*10
    __shared__ int part[1024];
    int t = threadIdx.x;
    int base = t * 10;
    int s = 0;
    if (t < 1000)
        for (int i = 0; i < 10; i++) s += g_deg[base + i];
    part[t] = s;
    __syncthreads();
    for (int d = 1; d < 1024; d <<= 1) {
        int v = (t >= d) ? part[t - d] : 0;
        __syncthreads();
        part[t] += v;
        __syncthreads();
    }
    int excl = (t == 0) ? 0 : part[t - 1];
    if (t < 1000) {
        int run = excl;
        for (int i = 0; i < 10; i++) { g_off[base + i] = run; run += g_deg[base + i]; }
        if (t == 999) g_off[NN] = run;
    }
}
__global__ void k_fill(const int* __restrict__ eidx) {
    int e = blockIdx.x * 256 + threadIdx.x;
    if (e < EE) {
        int r = eidx[EE + e];
        int s = eidx[e];
        int pos = atomicAdd(&g_cur[r], 1);
        int slot = g_off[r] + pos;
        g_elist[slot] = e;
        g_slist[slot] = s;
    }
}

// ---------------- h = node_feats @ W_up ------------------------------------
#define H_SMEM ((128 * 128 + 32 * 128) * 4)
__global__ __launch_bounds__(256) void k_h(const float* __restrict__ feats,
                                           const float* __restrict__ Wup) {
    extern __shared__ float sm[];
    float* sW = sm;
    float* sF = sm + 16384;
    int n0 = blockIdx.x * 32;
    int t = threadIdx.x;
    for (int i = t; i < 16384; i += 256) sW[i] = Wup[i];
    for (int i = t; i < 4096; i += 256) {
        int n = n0 + (i >> 7);
        sF[i] = (n < NN) ? feats[n * CC + (i & 127)] : 0.f;
    }
    __syncthreads();
    int tk = (t & 31) * 4;
    int tn = (t >> 5) * 4;
    float acc[4][4] = {};
    for (int u = 0; u < 128; u++) {
        float4 b = *(const float4*)&sW[u * 128 + tk];
        #pragma unroll
        for (int i = 0; i < 4; i++) {
            float a = sF[(tn + i) * 128 + u];
            acc[i][0] = fmaf(a, b.x, acc[i][0]);
            acc[i][1] = fmaf(a, b.y, acc[i][1]);
            acc[i][2] = fmaf(a, b.z, acc[i][2]);
            acc[i][3] = fmaf(a, b.w, acc[i][3]);
        }
    }
    #pragma unroll
    for (int i = 0; i < 4; i++) {
        int n = n0 + tn + i;
        if (n < NN) {
            float4 v = make_float4(acc[i][0], acc[i][1], acc[i][2], acc[i][3]);
            *(float4*)&g_h[n * CC + tk] = v;
        }
    }
}

// ---------------- sc --------------------------------------------------------
#define SC_SMEM ((32 * 128 + 320 + 32 * 80 + 80 * 128) * 4)
__global__ __launch_bounds__(256) void k_sc(const float* __restrict__ feats,
                                            const float* __restrict__ attrs,
                                            const float* __restrict__ Wskip,
                                            float* __restrict__ sc_out) {
    extern __shared__ float sm[];
    float* sF = sm;
    float* sA = sF + 4096;
    float* sX = sA + 320;
    float* sW = sX + 2560;
    int n0 = blockIdx.x * 32;
    int t = threadIdx.x;
    for (int i = t; i < 4096; i += 256) {
        int n = n0 + (i >> 7);
        sF[i] = (n < NN) ? feats[n * CC + (i & 127)] : 0.f;
    }
    for (int i = t; i < 320; i += 256) {
        int n = n0 + i / 10;
        sA[i] = (n < NN) ? attrs[n * AA + i % 10] : 0.f;
    }
    int tk = (t & 31) * 4;
    int tn = (t >> 5) * 4;
    float acc[4][4] = {};
    for (int uc = 0; uc < 16; uc++) {
        __syncthreads();
        for (int i = t; i < 10240; i += 256) sW[i] = Wskip[uc * 10240 + i];
        for (int idx = t; idx < 2560; idx += 256) {
            int n = idx / 80, i = idx % 80;
            sX[idx] = sF[n * 128 + uc * 8 + i / 10] * sA[n * 10 + i % 10];
        }
        __syncthreads();
        for (int i = 0; i < 80; i++) {
            float4 b = *(const float4*)&sW[i * 128 + tk];
            #pragma unroll
            for (int ii = 0; ii < 4; ii++) {
                float a = sX[(tn + ii) * 80 + i];
                acc[ii][0] = fmaf(a, b.x, acc[ii][0]);
                acc[ii][1] = fmaf(a, b.y, acc[ii][1]);
                acc[ii][2] = fmaf(a, b.z, acc[ii][2]);
                acc[ii][3] = fmaf(a, b.w, acc[ii][3]);
            }
        }
    }
    #pragma unroll
    for (int ii = 0; ii < 4; ii++) {
        int n = n0 + tn + ii;
        if (n < NN) {
            float4 v = make_float4(acc[ii][0], acc[ii][1], acc[ii][2], acc[ii][3]);
            *(float4*)&sc_out[n * CC + tk] = v;
        }
    }
}

// ---------------- fused edge MLP (persistent, f32x2, dup weights) ----------
// 512 threads, 128 edges / tile, activations [j][e].
// smem floats: W1 512 | W2d 8192 | W3d 8192 | W4 24576 | TA 8192 | TB 8192
// (EFt aliases TB).  Total 57856 floats = 231424 B.
#define MLP_NF (512 + 8192 + 8192 + 24576 + 8192 + 8192)
#define MLP_SMEM (MLP_NF * 4)
__global__ __launch_bounds__(512) void k_mlp(const float* __restrict__ ef,
                                             const float* __restrict__ W1,
                                             const float* __restrict__ W2,
                                             const float* __restrict__ W3,
                                             const float* __restrict__ W4) {
    extern __shared__ float sm[];
    float* sW1  = sm;             // 512
    float* sW2d = sW1 + 512;      // 8192  dup pairs: [u][2j..2j+1] = W2[u][j]
    float* sW3d = sW2d + 8192;    // 8192
    float* sW4  = sW3d + 8192;    // 24576
    float* sTA  = sW4 + 24576;    // 8192  [j][e]
    float* sTB  = sTA + 8192;     // 8192  [j][e]; also EFt [f][e] (8x128=1024)
    float* sEFt = sTB;
    int t = threadIdx.x;
    for (int i = t; i < 512; i += 512) sW1[i] = W1[i];
    for (int i = t; i < 8192; i += 512) {
        int u = i >> 7, jj = (i & 127) >> 1;
        sW2d[i] = W2[u * 64 + jj];
        sW3d[i] = W3[u * 64 + jj];
    }
    for (int i = t; i < 24576; i += 512) sW4[i] = W4[i];

    int j0c = (t & 15) * 4;        // layer2/3 j tile
    int elc = (t >> 4) * 4;        // layer2/3 edge tile

    for (int tile = blockIdx.x; tile < EE / 128; tile += gridDim.x) {
        int e0 = tile * 128;
        __syncthreads();
        // EFt [f][e] into TB region
        for (int i = t; i < 1024; i += 512) {
            int e = i >> 3, f = i & 7;
            sEFt[f * 128 + e] = ef[(e0 + e) * FF + f];
        }
        __syncthreads();
        // layer 1: sTA[j][e] = silu(sum_f EF[f][e] W1[f][j])
        for (int o = t; o < 8192; o += 512) {
            int j = o >> 7, e = o & 127;
            float acc = 0.f;
            #pragma unroll
            for (int f = 0; f < 8; f++) acc = fmaf(sEFt[f * 128 + e], sW1[f * 64 + j], acc);
            sTA[j * 128 + e] = silu(acc);
        }
        __syncthreads();
        // layer 2: sTB = silu(TA @ W2)  — dup-weight f32x2, zero movs
        {
            unsigned long long acc[2][4] = {};
            for (int u = 0; u < 64; u++) {
                ulonglong2 a  = *(const ulonglong2*)&sTA[u * 128 + elc];
                ulonglong2 wA = *(const ulonglong2*)&sW2d[u * 128 + j0c * 2];
                ulonglong2 wB = *(const ulonglong2*)&sW2d[u * 128 + j0c * 2 + 4];
                ffma2(acc[0][0], a.x, wA.x); ffma2(acc[1][0], a.y, wA.x);
                ffma2(acc[0][1], a.x, wA.y); ffma2(acc[1][1], a.y, wA.y);
                ffma2(acc[0][2], a.x, wB.x); ffma2(acc[1][2], a.y, wB.x);
                ffma2(acc[0][3], a.x, wB.y); ffma2(acc[1][3], a.y, wB.y);
            }
            #pragma unroll
            for (int jj = 0; jj < 4; jj++) {
                float f0, f1, f2, f3;
                unpack2(acc[0][jj], f0, f1);
                unpack2(acc[1][jj], f2, f3);
                float4 v = make_float4(silu(f0), silu(f1), silu(f2), silu(f3));
                *(float4*)&sTB[(j0c + jj) * 128 + elc] = v;
            }
        }
        __syncthreads();
        // layer 3: sTA = silu(TB @ W3)
        {
            unsigned long long acc[2][4] = {};
            for (int u = 0; u < 64; u++) {
                ulonglong2 a  = *(const ulonglong2*)&sTB[u * 128 + elc];
                ulonglong2 wA = *(const ulonglong2*)&sW3d[u * 128 + j0c * 2];
                ulonglong2 wB = *(const ulonglong2*)&sW3d[u * 128 + j0c * 2 + 4];
                ffma2(acc[0][0], a.x, wA.x); ffma2(acc[1][0], a.y, wA.x);
                ffma2(acc[0][1], a.x, wA.y); ffma2(acc[1][1], a.y, wA.y);
                ffma2(acc[0][2], a.x, wB.x); ffma2(acc[1][2], a.y, wB.x);
                ffma2(acc[0][3], a.x, wB.y); ffma2(acc[1][3], a.y, wB.y);
            }
            #pragma unroll
            for (int jj = 0; jj < 4; jj++) {
                float f0, f1, f2, f3;
                unpack2(acc[0][jj], f0, f1);
                unpack2(acc[1][jj], f2, f3);
                float4 v = make_float4(silu(f0), silu(f1), silu(f2), silu(f3));
                *(float4*)&sTA[(j0c + jj) * 128 + elc] = v;
            }
        }
        __syncthreads();
        // layer 4: tpw[e][j] = TA^T @ W4 — j-pair f32x2 (w native pairs)
        for (int rep = 0; rep < 6; rep++) {
            int tl = rep * 512 + t;
            int jt = tl % 48, et = tl / 48;   // et 0..63
            int j0 = jt * 8, el = et * 2;
            unsigned long long acc[2][4] = {};
            for (int u = 0; u < 64; u++) {
                float a0 = sTA[u * 128 + el];
                float a1 = sTA[u * 128 + el + 1];
                unsigned long long A0 = pack2(a0, a0);
                unsigned long long A1 = pack2(a1, a1);
                ulonglong2 w01 = *(const ulonglong2*)&sW4[u * 384 + j0];
                ulonglong2 w23 = *(const ulonglong2*)&sW4[u * 384 + j0 + 4];
                ffma2(acc[0][0], A0, w01.x); ffma2(acc[1][0], A1, w01.x);
                ffma2(acc[0][1], A0, w01.y); ffma2(acc[1][1], A1, w01.y);
                ffma2(acc[0][2], A0, w23.x); ffma2(acc[1][2], A1, w23.x);
                ffma2(acc[0][3], A0, w23.y); ffma2(acc[1][3], A1, w23.y);
            }
            #pragma unroll
            for (int ee = 0; ee < 2; ee++) {
                float f0, f1, f2, f3, f4, f5, f6, f7;
                unpack2(acc[ee][0], f0, f1);
                unpack2(acc[ee][1], f2, f3);
                unpack2(acc[ee][2], f4, f5);
                unpack2(acc[ee][3], f6, f7);
                long base = (long)(e0 + el + ee) * 384 + j0;
                *(float4*)&g_tpw[base]     = make_float4(f0, f1, f2, f3);
                *(float4*)&g_tpw[base + 4] = make_float4(f4, f5, f6, f7);
            }
        }
    }
}

// ---------------- gather conv_tp + segment_sum -----------------------------
// 1 warp per node, 4 channels/thread. 8 nodes / 256-thread block.
__global__ __launch_bounds__(256) void k_gather(const float* __restrict__ yr,
                                                const float* __restrict__ yi) {
    int t = threadIdx.x;
    int n = blockIdx.x * 8 + (t >> 5);
    int c0 = (t & 31) * 4;
    float4 ar[9], ai[9];
    #pragma unroll
    for (int m = 0; m < 9; m++) {
        ar[m] = make_float4(0.f, 0.f, 0.f, 0.f);
        ai[m] = make_float4(0.f, 0.f, 0.f, 0.f);
    }
    int beg = g_off[n], end = g_off[n + 1];
    #pragma unroll 2
    for (int i = beg; i < end; i++) {
        int e = g_elist[i];
        int s = g_slist[i];
        float4 x  = *(const float4*)&g_h[s * CC + c0];
        const float* tw = g_tpw + (long)e * 384;
        float4 t0 = *(const float4*)&tw[c0];
        float4 t1 = *(const float4*)&tw[128 + c0];
        float4 t2 = *(const float4*)&tw[256 + c0];
        float4 xw0 = make_float4(x.x * t0.x, x.y * t0.y, x.z * t0.z, x.w * t0.w);
        float4 xw1 = make_float4(x.x * t1.x, x.y * t1.y, x.z * t1.z, x.w * t1.w);
        float4 xw2 = make_float4(x.x * t2.x, x.y * t2.y, x.z * t2.z, x.w * t2.w);
        const float* yre = yr + e * 9;
        const float* yie = yi + e * 9;
        #pragma unroll
        for (int m = 0; m < 9; m++) {
            float4 xw = (m == 0) ? xw0 : (m < 4) ? xw1 : xw2;
            float vr = yre[m], vi = yie[m];
            ar[m].x = fmaf(xw.x, vr, ar[m].x); ar[m].y = fmaf(xw.y, vr, ar[m].y);
            ar[m].z = fmaf(xw.z, vr, ar[m].z); ar[m].w = fmaf(xw.w, vr, ar[m].w);
            ai[m].x = fmaf(xw.x, vi, ai[m].x); ai[m].y = fmaf(xw.y, vi, ai[m].y);
            ai[m].z = fmaf(xw.z, vi, ai[m].z); ai[m].w = fmaf(xw.w, vi, ai[m].w);
        }
    }
    float* mr = g_msg_r + n * MSGW;
    float* mi = g_msg_i + n * MSGW;
    *(float4*)&mr[c0] = ar[0];
    *(float4*)&mi[c0] = ai[0];
    #pragma unroll
    for (int m = 0; m < 3; m++) {
        *(float4*)&mr[128 + m * 128 + c0] = ar[1 + m];
        *(float4*)&mi[128 + m * 128 + c0] = ai[1 + m];
    }
    #pragma unroll
    for (int m = 0; m < 5; m++) {
        *(float4*)&mr[512 + m * 128 + c0] = ar[4 + m];
        *(float4*)&mi[512 + m * 128 + c0] = ai[4 + m];
    }
}

// ---------------- linear_irreps (persistent, fused r+i) --------------------
#define LIN_SMEM ((128 * 128 + 2 * 32 * 128) * 4)
__global__ __launch_bounds__(256) void k_linear(const float* __restrict__ W,
                                                float* __restrict__ out_r,
                                                float* __restrict__ out_i,
                                                int d, int loff, int moff) {
    extern __shared__ float sm[];
    float* sW  = sm;              // 16384
    float* sAr = sm + 16384;      // 4096
    float* sAi = sAr + 4096;      // 4096
    int nrows = NN * d;
    int t = threadIdx.x;
    for (int i = t; i < 16384; i += 256) sW[i] = W[i];
    int tk = (t & 31) * 4;
    int tr = (t >> 5) * 4;
    for (int r0 = blockIdx.x * 32; r0 < nrows; r0 += gridDim.x * 32) {
        __syncthreads();
        for (int i = t; i < 4096; i += 256) {
            int rl = i >> 7, u = i & 127;
            int row = r0 + rl;
            float vr = 0.f, vi = 0.f;
            if (row < nrows) {
                int n = row / d, m = row % d;
                int off = n * MSGW + loff + m * 128 + u;
                vr = g_msg_r[off];
                vi = g_msg_i[off];
            }
            sAr[i] = vr;
            sAi[i] = vi;
        }
        __syncthreads();
        float accr[4][4] = {};
        float acci[4][4] = {};
        for (int u = 0; u < 128; u++) {
            float4 b = *(const float4*)&sW[u * 128 + tk];
            #pragma unroll
            for (int i = 0; i < 4; i++) {
                float a = sAr[(tr + i) * 128 + u];
                accr[i][0] = fmaf(a, b.x, accr[i][0]);
                accr[i][1] = fmaf(a, b.y, accr[i][1]);
                accr[i][2] = fmaf(a, b.z, accr[i][2]);
                accr[i][3] = fmaf(a, b.w, accr[i][3]);
                float c = sAi[(tr + i) * 128 + u];
                acci[i][0] = fmaf(c, b.x, acci[i][0]);
                acci[i][1] = fmaf(c, b.y, acci[i][1]);
                acci[i][2] = fmaf(c, b.z, acci[i][2]);
                acci[i][3] = fmaf(c, b.w, acci[i][3]);
            }
        }
        #pragma unroll
        for (int i = 0; i < 4; i++) {
            int row = r0 + tr + i;
            if (row < nrows) {
                int n = row / d, m = row % d;
                float* orp = out_r + n * MSGW + moff + m;
                float* oip = out_i + n * MSGW + moff + m;
                #pragma unroll
                for (int j = 0; j < 4; j++) {
                    orp[(tk + j) * 9] = accr[i][j];
                    oip[(tk + j) * 9] = acci[i][j];
                }
            }
        }
    }
}

// ---------------- launch ---------------------------------------------------
extern "C" void kernel_launch(void* const* d_in, const int* in_sizes, int n_in,
                              void* d_out, int out_size) {
    const float* node_attrs = (const float*)d_in[0];
    const float* node_feats = (const float*)d_in[1];
    const float* yr        = (const float*)d_in[2];
    const float* yi        = (const float*)d_in[3];
    const float* ef        = (const float*)d_in[4];
    const int*   eidx      = (const int*)  d_in[5];
    const float* Wup       = (const float*)d_in[6];
    const float* Wskip     = (const float*)d_in[7];
    const float* W1        = (const float*)d_in[8];
    const float* W2        = (const float*)d_in[9];
    const float* W3        = (const float*)d_in[10];
    const float* W4        = (const float*)d_in[11];
    const float* Wl0       = (const float*)d_in[12];
    const float* Wl1       = (const float*)d_in[13];
    const float* Wl2       = (const float*)d_in[14];

    float* out   = (float*)d_out;
    float* out_r = out;
    float* out_i = out + OUTR_ELEMS;
    float* out_s = out + 2 * OUTR_ELEMS;

    cudaFuncSetAttribute(k_h,      cudaFuncAttributeMaxDynamicSharedMemorySize, H_SMEM);
    cudaFuncSetAttribute(k_sc,     cudaFuncAttributeMaxDynamicSharedMemorySize, SC_SMEM);
    cudaFuncSetAttribute(k_mlp,    cudaFuncAttributeMaxDynamicSharedMemorySize, MLP_SMEM);
    cudaFuncSetAttribute(k_linear, cudaFuncAttributeMaxDynamicSharedMemorySize, LIN_SMEM);

    // idx 0..2: CSR prep
    k_reset<<<(NN + 255) / 256, 256>>>();
    k_count<<<(EE + 255) / 256, 256>>>(eidx);
    k_scan<<<1, 1024>>>();
    // idx 3: k_mlp — placed here so the ncu window (4th launch) profiles it
    k_mlp<<<148, 512, MLP_SMEM>>>(ef, W1, W2, W3, W4);
    // idx 4..6
    k_fill<<<(EE + 255) / 256, 256>>>(eidx);
    k_h<<<(NN + 31) / 32, 256, H_SMEM>>>(node_feats, Wup);
    k_sc<<<(NN + 31) / 32, 256, SC_SMEM>>>(node_feats, node_attrs, Wskip, out_s);
    // idx 7
    k_gather<<<NN / 8, 256>>>(yr, yi);
    // idx 8..10
    k_linear<<<296, 256, LIN_SMEM>>>(Wl0, out_r, out_i, 1, 0,   0);
    k_linear<<<296, 256, LIN_SMEM>>>(Wl1, out_r, out_i, 3, 128, 1);
    k_linear<<<296, 256, LIN_SMEM>>>(Wl2, out_r, out_i, 5, 512, 4);
}

// round 6
// speedup vs baseline: 1.2499x; 1.2499x over previous
#include <cuda_runtime.h>
#include <cuda_bf16.h>
#include <cstdint>

// Problem constants
#define NN 10000
#define EE 128000
#define CC 128
#define AA 10
#define FF 8
#define MSGW 1152
#define OUTR_ELEMS (NN * CC * 9)

// ---------------- scratch (device globals) ---------------------------------
__device__ float g_h[NN * CC];
__device__ float g_tpw[(long)EE * 384];
__device__ float g_msg_r[NN * MSGW];
__device__ float g_msg_i[NN * MSGW];
__device__ int   g_deg[NN];
__device__ int   g_cur[NN];
__device__ int   g_off[NN + 1];
__device__ int   g_elist[EE];
__device__ int   g_slist[EE];
// T3 activations transposed [u][e] (64 x 128000 fp32)
__device__ float g_t3t[64 * EE];

__device__ __forceinline__ float silu(float x) {
    return x * (1.0f / (1.0f + __expf(-x)));
}

// f32x2 packed helpers
__device__ __forceinline__ unsigned long long pack2(float lo, float hi) {
    unsigned long long r;
    asm("mov.b64 %0, {%1, %2};" : "=l"(r) : "f"(lo), "f"(hi));
    return r;
}
__device__ __forceinline__ void unpack2(unsigned long long v, float& lo, float& hi) {
    asm("mov.b64 {%0, %1}, %2;" : "=f"(lo), "=f"(hi) : "l"(v));
}
__device__ __forceinline__ void ffma2(unsigned long long& acc,
                                      unsigned long long a, unsigned long long b) {
    asm("fma.rn.f32x2 %0, %1, %2, %0;" : "+l"(acc) : "l"(a), "l"(b));
}

// ---------------- CSR build -------------------------------------------------
__global__ void k_reset() {
    int t = blockIdx.x * 256 + threadIdx.x;
    if (t < NN) { g_deg[t] = 0; g_cur[t] = 0; }
}
__global__ void k_count(const int* __restrict__ eidx) {
    int e = blockIdx.x * 256 + threadIdx.x;
    if (e < EE) atomicAdd(&g_deg[eidx[EE + e]], 1);
}
__global__ void k_scan() {
    __shared__ int part[1024];
    int t = threadIdx.x;
    int base = t * 10;
    int s = 0;
    if (t < 1000)
        for (int i = 0; i < 10; i++) s += g_deg[base + i];
    part[t] = s;
    __syncthreads();
    for (int d = 1; d < 1024; d <<= 1) {
        int v = (t >= d) ? part[t - d] : 0;
        __syncthreads();
        part[t] += v;
        __syncthreads();
    }
    int excl = (t == 0) ? 0 : part[t - 1];
    if (t < 1000) {
        int run = excl;
        for (int i = 0; i < 10; i++) { g_off[base + i] = run; run += g_deg[base + i]; }
        if (t == 999) g_off[NN] = run;
    }
}
__global__ void k_fill(const int* __restrict__ eidx) {
    int e = blockIdx.x * 256 + threadIdx.x;
    if (e < EE) {
        int r = eidx[EE + e];
        int s = eidx[e];
        int pos = atomicAdd(&g_cur[r], 1);
        int slot = g_off[r] + pos;
        g_elist[slot] = e;
        g_slist[slot] = s;
    }
}

// ---------------- h = node_feats @ W_up ------------------------------------
#define H_SMEM ((128 * 128 + 32 * 128) * 4)
__global__ __launch_bounds__(256) void k_h(const float* __restrict__ feats,
                                           const float* __restrict__ Wup) {
    extern __shared__ float sm[];
    float* sW = sm;
    float* sF = sm + 16384;
    int n0 = blockIdx.x * 32;
    int t = threadIdx.x;
    for (int i = t; i < 16384; i += 256) sW[i] = Wup[i];
    for (int i = t; i < 4096; i += 256) {
        int n = n0 + (i >> 7);
        sF[i] = (n < NN) ? feats[n * CC + (i & 127)] : 0.f;
    }
    __syncthreads();
    int tk = (t & 31) * 4;
    int tn = (t >> 5) * 4;
    float acc[4][4] = {};
    for (int u = 0; u < 128; u++) {
        float4 b = *(const float4*)&sW[u * 128 + tk];
        #pragma unroll
        for (int i = 0; i < 4; i++) {
            float a = sF[(tn + i) * 128 + u];
            acc[i][0] = fmaf(a, b.x, acc[i][0]);
            acc[i][1] = fmaf(a, b.y, acc[i][1]);
            acc[i][2] = fmaf(a, b.z, acc[i][2]);
            acc[i][3] = fmaf(a, b.w, acc[i][3]);
        }
    }
    #pragma unroll
    for (int i = 0; i < 4; i++) {
        int n = n0 + tn + i;
        if (n < NN) {
            float4 v = make_float4(acc[i][0], acc[i][1], acc[i][2], acc[i][3]);
            *(float4*)&g_h[n * CC + tk] = v;
        }
    }
}

// ---------------- sc --------------------------------------------------------
#define SC_SMEM ((32 * 128 + 320 + 32 * 80 + 80 * 128) * 4)
__global__ __launch_bounds__(256) void k_sc(const float* __restrict__ feats,
                                            const float* __restrict__ attrs,
                                            const float* __restrict__ Wskip,
                                            float* __restrict__ sc_out) {
    extern __shared__ float sm[];
    float* sF = sm;
    float* sA = sF + 4096;
    float* sX = sA + 320;
    float* sW = sX + 2560;
    int n0 = blockIdx.x * 32;
    int t = threadIdx.x;
    for (int i = t; i < 4096; i += 256) {
        int n = n0 + (i >> 7);
        sF[i] = (n < NN) ? feats[n * CC + (i & 127)] : 0.f;
    }
    for (int i = t; i < 320; i += 256) {
        int n = n0 + i / 10;
        sA[i] = (n < NN) ? attrs[n * AA + i % 10] : 0.f;
    }
    int tk = (t & 31) * 4;
    int tn = (t >> 5) * 4;
    float acc[4][4] = {};
    for (int uc = 0; uc < 16; uc++) {
        __syncthreads();
        for (int i = t; i < 10240; i += 256) sW[i] = Wskip[uc * 10240 + i];
        for (int idx = t; idx < 2560; idx += 256) {
            int n = idx / 80, i = idx % 80;
            sX[idx] = sF[n * 128 + uc * 8 + i / 10] * sA[n * 10 + i % 10];
        }
        __syncthreads();
        for (int i = 0; i < 80; i++) {
            float4 b = *(const float4*)&sW[i * 128 + tk];
            #pragma unroll
            for (int ii = 0; ii < 4; ii++) {
                float a = sX[(tn + ii) * 80 + i];
                acc[ii][0] = fmaf(a, b.x, acc[ii][0]);
                acc[ii][1] = fmaf(a, b.y, acc[ii][1]);
                acc[ii][2] = fmaf(a, b.z, acc[ii][2]);
                acc[ii][3] = fmaf(a, b.w, acc[ii][3]);
            }
        }
    }
    #pragma unroll
    for (int ii = 0; ii < 4; ii++) {
        int n = n0 + tn + ii;
        if (n < NN) {
            float4 v = make_float4(acc[ii][0], acc[ii][1], acc[ii][2], acc[ii][3]);
            *(float4*)&sc_out[n * CC + tk] = v;
        }
    }
}

// ---------------- MLP layers 1-3 (70 KB smem, 3 CTA/SM) --------------------
// 256 threads, 64 edges / block.  Writes T3 transposed to g_t3t[u][e].
#define MLP_SMEM ((512 + 4096 + 4096 + 512 + 4096 + 4096) * 4)
__global__ __launch_bounds__(256) void k_mlp123(const float* __restrict__ ef,
                                                const float* __restrict__ W1,
                                                const float* __restrict__ W2,
                                                const float* __restrict__ W3) {
    extern __shared__ float sm[];
    float* sW1 = sm;               // 512
    float* sW2 = sW1 + 512;        // 4096
    float* sW3 = sW2 + 4096;       // 4096
    float* sEF = sW3 + 4096;       // 512
    float* sTA = sEF + 512;        // 4096
    float* sTB = sTA + 4096;       // 4096
    // T3 transposed staging reuses sEF+sTA region (4608 floats >= 64*65=4160)
    float* sT3 = sEF;
    int t = threadIdx.x;
    for (int i = t; i < 512; i += 256) sW1[i] = W1[i];
    for (int i = t; i < 4096; i += 256) sW2[i] = W2[i];
    for (int i = t; i < 4096; i += 256) sW3[i] = W3[i];
    int e0 = blockIdx.x * 64;
    for (int i = t; i < 512; i += 256) sEF[i] = ef[e0 * FF + i];
    __syncthreads();
    // layer 1
    for (int o = t; o < 4096; o += 256) {
        int e = o >> 6, j = o & 63;
        float acc = 0.f;
        #pragma unroll
        for (int f = 0; f < 8; f++) acc = fmaf(sEF[e * 8 + f], sW1[f * 64 + j], acc);
        sTA[o] = silu(acc);
    }
    __syncthreads();
    int j0 = (t & 15) * 4, el = (t >> 4) * 4;
    // layer 2: sTB = silu(sTA @ W2)
    {
        float acc[4][4] = {};
        for (int u = 0; u < 64; u++) {
            float4 b = *(const float4*)&sW2[u * 64 + j0];
            #pragma unroll
            for (int i = 0; i < 4; i++) {
                float a = sTA[(el + i) * 64 + u];
                acc[i][0] = fmaf(a, b.x, acc[i][0]);
                acc[i][1] = fmaf(a, b.y, acc[i][1]);
                acc[i][2] = fmaf(a, b.z, acc[i][2]);
                acc[i][3] = fmaf(a, b.w, acc[i][3]);
            }
        }
        #pragma unroll
        for (int i = 0; i < 4; i++)
            #pragma unroll
            for (int j = 0; j < 4; j++) sTB[(el + i) * 64 + j0 + j] = silu(acc[i][j]);
    }
    __syncthreads();
    // layer 3: read sTB, write transposed silu(acc) into sT3[j][e] (stride 65)
    {
        float acc[4][4] = {};
        for (int u = 0; u < 64; u++) {
            float4 b = *(const float4*)&sW3[u * 64 + j0];
            #pragma unroll
            for (int i = 0; i < 4; i++) {
                float a = sTB[(el + i) * 64 + u];
                acc[i][0] = fmaf(a, b.x, acc[i][0]);
                acc[i][1] = fmaf(a, b.y, acc[i][1]);
                acc[i][2] = fmaf(a, b.z, acc[i][2]);
                acc[i][3] = fmaf(a, b.w, acc[i][3]);
            }
        }
        // sT3 region (sEF/sTA) is dead now; writes are disjoint from sTB reads
        #pragma unroll
        for (int i = 0; i < 4; i++)
            #pragma unroll
            for (int j = 0; j < 4; j++)
                sT3[(j0 + j) * 65 + el + i] = silu(acc[i][j]);
    }
    __syncthreads();
    // coalesced store: g_t3t[u][e0+e]
    for (int i = t; i < 4096; i += 256) {
        int u = i >> 6, e = i & 63;
        g_t3t[u * EE + e0 + e] = sT3[u * 65 + e];
    }
}

// ---------------- layer 4 GEMM: tpw = T3 @ W4 (f32x2, 8x8 tiles) -----------
// Block: 128 edges x 384 j (3 passes of 128 j), K=64.  256 threads.
// smem: W4 full (64x384 = 96 KB) + A tile (64x128 = 32 KB) = 128 KB.
#define G4_SMEM ((24576 + 8192) * 4)
__global__ __launch_bounds__(256) void k_gemm4(const float* __restrict__ W4) {
    extern __shared__ float sm[];
    float* sW = sm;            // 24576
    float* sA = sm + 24576;    // 64 x 128
    int t = threadIdx.x;
    int e0 = blockIdx.x * 128;
    for (int i = t; i < 24576; i += 256) sW[i] = W4[i];
    for (int i = t; i < 2048; i += 256) {
        int u = i >> 5, e4 = (i & 31) * 4;
        *(float4*)&sA[u * 128 + e4] = *(const float4*)&g_t3t[u * EE + e0 + e4];
    }
    __syncthreads();
    int jg = t & 15, eg = t >> 4;
    int el = eg * 8;
    #pragma unroll 1
    for (int pass = 0; pass < 3; pass++) {
        int jb = pass * 128 + jg * 8;
        unsigned long long acc[8][4] = {};
        #pragma unroll 4
        for (int u = 0; u < 64; u++) {
            float4 a03 = *(const float4*)&sA[u * 128 + el];
            float4 a47 = *(const float4*)&sA[u * 128 + el + 4];
            ulonglong2 wA = *(const ulonglong2*)&sW[u * 384 + jb];
            ulonglong2 wB = *(const ulonglong2*)&sW[u * 384 + jb + 4];
            unsigned long long A0 = pack2(a03.x, a03.x);
            unsigned long long A1 = pack2(a03.y, a03.y);
            unsigned long long A2 = pack2(a03.z, a03.z);
            unsigned long long A3 = pack2(a03.w, a03.w);
            unsigned long long A4 = pack2(a47.x, a47.x);
            unsigned long long A5 = pack2(a47.y, a47.y);
            unsigned long long A6 = pack2(a47.z, a47.z);
            unsigned long long A7 = pack2(a47.w, a47.w);
            ffma2(acc[0][0], A0, wA.x); ffma2(acc[0][1], A0, wA.y);
            ffma2(acc[0][2], A0, wB.x); ffma2(acc[0][3], A0, wB.y);
            ffma2(acc[1][0], A1, wA.x); ffma2(acc[1][1], A1, wA.y);
            ffma2(acc[1][2], A1, wB.x); ffma2(acc[1][3], A1, wB.y);
            ffma2(acc[2][0], A2, wA.x); ffma2(acc[2][1], A2, wA.y);
            ffma2(acc[2][2], A2, wB.x); ffma2(acc[2][3], A2, wB.y);
            ffma2(acc[3][0], A3, wA.x); ffma2(acc[3][1], A3, wA.y);
            ffma2(acc[3][2], A3, wB.x); ffma2(acc[3][3], A3, wB.y);
            ffma2(acc[4][0], A4, wA.x); ffma2(acc[4][1], A4, wA.y);
            ffma2(acc[4][2], A4, wB.x); ffma2(acc[4][3], A4, wB.y);
            ffma2(acc[5][0], A5, wA.x); ffma2(acc[5][1], A5, wA.y);
            ffma2(acc[5][2], A5, wB.x); ffma2(acc[5][3], A5, wB.y);
            ffma2(acc[6][0], A6, wA.x); ffma2(acc[6][1], A6, wA.y);
            ffma2(acc[6][2], A6, wB.x); ffma2(acc[6][3], A6, wB.y);
            ffma2(acc[7][0], A7, wA.x); ffma2(acc[7][1], A7, wA.y);
            ffma2(acc[7][2], A7, wB.x); ffma2(acc[7][3], A7, wB.y);
        }
        #pragma unroll
        for (int i = 0; i < 8; i++) {
            float f0, f1, f2, f3, f4, f5, f6, f7;
            unpack2(acc[i][0], f0, f1);
            unpack2(acc[i][1], f2, f3);
            unpack2(acc[i][2], f4, f5);
            unpack2(acc[i][3], f6, f7);
            long base = (long)(e0 + el + i) * 384 + jb;
            *(float4*)&g_tpw[base]     = make_float4(f0, f1, f2, f3);
            *(float4*)&g_tpw[base + 4] = make_float4(f4, f5, f6, f7);
        }
    }
}

// ---------------- gather conv_tp + segment_sum -----------------------------
__global__ __launch_bounds__(256) void k_gather(const float* __restrict__ yr,
                                                const float* __restrict__ yi) {
    int t = threadIdx.x;
    int n = blockIdx.x * 8 + (t >> 5);
    int c0 = (t & 31) * 4;
    float4 ar[9], ai[9];
    #pragma unroll
    for (int m = 0; m < 9; m++) {
        ar[m] = make_float4(0.f, 0.f, 0.f, 0.f);
        ai[m] = make_float4(0.f, 0.f, 0.f, 0.f);
    }
    int beg = g_off[n], end = g_off[n + 1];
    #pragma unroll 2
    for (int i = beg; i < end; i++) {
        int e = g_elist[i];
        int s = g_slist[i];
        float4 x  = *(const float4*)&g_h[s * CC + c0];
        const float* tw = g_tpw + (long)e * 384;
        float4 t0 = *(const float4*)&tw[c0];
        float4 t1 = *(const float4*)&tw[128 + c0];
        float4 t2 = *(const float4*)&tw[256 + c0];
        float4 xw0 = make_float4(x.x * t0.x, x.y * t0.y, x.z * t0.z, x.w * t0.w);
        float4 xw1 = make_float4(x.x * t1.x, x.y * t1.y, x.z * t1.z, x.w * t1.w);
        float4 xw2 = make_float4(x.x * t2.x, x.y * t2.y, x.z * t2.z, x.w * t2.w);
        const float* yre = yr + e * 9;
        const float* yie = yi + e * 9;
        #pragma unroll
        for (int m = 0; m < 9; m++) {
            float4 xw = (m == 0) ? xw0 : (m < 4) ? xw1 : xw2;
            float vr = yre[m], vi = yie[m];
            ar[m].x = fmaf(xw.x, vr, ar[m].x); ar[m].y = fmaf(xw.y, vr, ar[m].y);
            ar[m].z = fmaf(xw.z, vr, ar[m].z); ar[m].w = fmaf(xw.w, vr, ar[m].w);
            ai[m].x = fmaf(xw.x, vi, ai[m].x); ai[m].y = fmaf(xw.y, vi, ai[m].y);
            ai[m].z = fmaf(xw.z, vi, ai[m].z); ai[m].w = fmaf(xw.w, vi, ai[m].w);
        }
    }
    float* mr = g_msg_r + n * MSGW;
    float* mi = g_msg_i + n * MSGW;
    *(float4*)&mr[c0] = ar[0];
    *(float4*)&mi[c0] = ai[0];
    #pragma unroll
    for (int m = 0; m < 3; m++) {
        *(float4*)&mr[128 + m * 128 + c0] = ar[1 + m];
        *(float4*)&mi[128 + m * 128 + c0] = ai[1 + m];
    }
    #pragma unroll
    for (int m = 0; m < 5; m++) {
        *(float4*)&mr[512 + m * 128 + c0] = ar[4 + m];
        *(float4*)&mi[512 + m * 128 + c0] = ai[4 + m];
    }
}

// ---------------- linear_irreps (persistent, fused r+i) --------------------
#define LIN_SMEM ((128 * 128 + 2 * 32 * 128) * 4)
__global__ __launch_bounds__(256) void k_linear(const float* __restrict__ W,
                                                float* __restrict__ out_r,
                                                float* __restrict__ out_i,
                                                int d, int loff, int moff) {
    extern __shared__ float sm[];
    float* sW  = sm;
    float* sAr = sm + 16384;
    float* sAi = sAr + 4096;
    int nrows = NN * d;
    int t = threadIdx.x;
    for (int i = t; i < 16384; i += 256) sW[i] = W[i];
    int tk = (t & 31) * 4;
    int tr = (t >> 5) * 4;
    for (int r0 = blockIdx.x * 32; r0 < nrows; r0 += gridDim.x * 32) {
        __syncthreads();
        for (int i = t; i < 4096; i += 256) {
            int rl = i >> 7, u = i & 127;
            int row = r0 + rl;
            float vr = 0.f, vi = 0.f;
            if (row < nrows) {
                int n = row / d, m = row % d;
                int off = n * MSGW + loff + m * 128 + u;
                vr = g_msg_r[off];
                vi = g_msg_i[off];
            }
            sAr[i] = vr;
            sAi[i] = vi;
        }
        __syncthreads();
        float accr[4][4] = {};
        float acci[4][4] = {};
        for (int u = 0; u < 128; u++) {
            float4 b = *(const float4*)&sW[u * 128 + tk];
            #pragma unroll
            for (int i = 0; i < 4; i++) {
                float a = sAr[(tr + i) * 128 + u];
                accr[i][0] = fmaf(a, b.x, accr[i][0]);
                accr[i][1] = fmaf(a, b.y, accr[i][1]);
                accr[i][2] = fmaf(a, b.z, accr[i][2]);
                accr[i][3] = fmaf(a, b.w, accr[i][3]);
                float c = sAi[(tr + i) * 128 + u];
                acci[i][0] = fmaf(c, b.x, acci[i][0]);
                acci[i][1] = fmaf(c, b.y, acci[i][1]);
                acci[i][2] = fmaf(c, b.z, acci[i][2]);
                acci[i][3] = fmaf(c, b.w, acci[i][3]);
            }
        }
        #pragma unroll
        for (int i = 0; i < 4; i++) {
            int row = r0 + tr + i;
            if (row < nrows) {
                int n = row / d, m = row % d;
                float* orp = out_r + n * MSGW + moff + m;
                float* oip = out_i + n * MSGW + moff + m;
                #pragma unroll
                for (int j = 0; j < 4; j++) {
                    orp[(tk + j) * 9] = accr[i][j];
                    oip[(tk + j) * 9] = acci[i][j];
                }
            }
        }
    }
}

// ---------------- launch ---------------------------------------------------
extern "C" void kernel_launch(void* const* d_in, const int* in_sizes, int n_in,
                              void* d_out, int out_size) {
    const float* node_attrs = (const float*)d_in[0];
    const float* node_feats = (const float*)d_in[1];
    const float* yr        = (const float*)d_in[2];
    const float* yi        = (const float*)d_in[3];
    const float* ef        = (const float*)d_in[4];
    const int*   eidx      = (const int*)  d_in[5];
    const float* Wup       = (const float*)d_in[6];
    const float* Wskip     = (const float*)d_in[7];
    const float* W1        = (const float*)d_in[8];
    const float* W2        = (const float*)d_in[9];
    const float* W3        = (const float*)d_in[10];
    const float* W4        = (const float*)d_in[11];
    const float* Wl0       = (const float*)d_in[12];
    const float* Wl1       = (const float*)d_in[13];
    const float* Wl2       = (const float*)d_in[14];

    float* out   = (float*)d_out;
    float* out_r = out;
    float* out_i = out + OUTR_ELEMS;
    float* out_s = out + 2 * OUTR_ELEMS;

    cudaFuncSetAttribute(k_h,      cudaFuncAttributeMaxDynamicSharedMemorySize, H_SMEM);
    cudaFuncSetAttribute(k_sc,     cudaFuncAttributeMaxDynamicSharedMemorySize, SC_SMEM);
    cudaFuncSetAttribute(k_mlp123, cudaFuncAttributeMaxDynamicSharedMemorySize, MLP_SMEM);
    cudaFuncSetAttribute(k_gemm4,  cudaFuncAttributeMaxDynamicSharedMemorySize, G4_SMEM);
    cudaFuncSetAttribute(k_linear, cudaFuncAttributeMaxDynamicSharedMemorySize, LIN_SMEM);

    // idx 0..2
    k_mlp123<<<EE / 64, 256, MLP_SMEM>>>(ef, W1, W2, W3);
    k_reset<<<(NN + 255) / 256, 256>>>();
    k_count<<<(EE + 255) / 256, 256>>>(eidx);
    // idx 3: profiled launch
    k_gemm4<<<EE / 128, 256, G4_SMEM>>>(W4);
    // idx 4..7
    k_scan<<<1, 1024>>>();
    k_fill<<<(EE + 255) / 256, 256>>>(eidx);
    k_h<<<(NN + 31) / 32, 256, H_SMEM>>>(node_feats, Wup);
    k_sc<<<(NN + 31) / 32, 256, SC_SMEM>>>(node_feats, node_attrs, Wskip, out_s);
    // idx 8
    k_gather<<<NN / 8, 256>>>(yr, yi);
    // idx 9..11
    k_linear<<<296, 256, LIN_SMEM>>>(Wl0, out_r, out_i, 1, 0,   0);
    k_linear<<<296, 256, LIN_SMEM>>>(Wl1, out_r, out_i, 3, 128, 1);
    k_linear<<<296, 256, LIN_SMEM>>>(Wl2, out_r, out_i, 5, 512, 4);
}

// round 7
// speedup vs baseline: 1.3414x; 1.0731x over previous
#include <cuda_runtime.h>
#include <cuda_bf16.h>
#include <cstdint>

// Problem constants
#define NN 10000
#define EE 128000
#define CC 128
#define AA 10
#define FF 8
#define MSGW 1152
#define OUTR_ELEMS (NN * CC * 9)

// ---------------- scratch (device globals) ---------------------------------
__device__ float g_h[NN * CC];
__device__ float g_tpw[(long)EE * 384];
__device__ float g_msg_r[NN * MSGW];
__device__ float g_msg_i[NN * MSGW];
__device__ int   g_deg[NN];
__device__ int   g_cur[NN];
__device__ int   g_off[NN + 1];
__device__ int   g_elist[EE];
__device__ int   g_slist[EE];
// T3 activations transposed [u][e] (64 x 128000 fp32)
__device__ float g_t3t[64 * EE];

__device__ __forceinline__ float silu(float x) {
    return x * (1.0f / (1.0f + __expf(-x)));
}

// f32x2 packed helpers
__device__ __forceinline__ unsigned long long pack2(float lo, float hi) {
    unsigned long long r;
    asm("mov.b64 %0, {%1, %2};" : "=l"(r) : "f"(lo), "f"(hi));
    return r;
}
__device__ __forceinline__ void unpack2(unsigned long long v, float& lo, float& hi) {
    asm("mov.b64 {%0, %1}, %2;" : "=f"(lo), "=f"(hi) : "l"(v));
}
__device__ __forceinline__ void ffma2(unsigned long long& acc,
                                      unsigned long long a, unsigned long long b) {
    asm("fma.rn.f32x2 %0, %1, %2, %0;" : "+l"(acc) : "l"(a), "l"(b));
}

// ---------------- CSR build -------------------------------------------------
__global__ void k_reset() {
    int t = blockIdx.x * 256 + threadIdx.x;
    if (t < NN) { g_deg[t] = 0; g_cur[t] = 0; }
}
__global__ void k_count(const int* __restrict__ eidx) {
    int e = blockIdx.x * 256 + threadIdx.x;
    if (e < EE) atomicAdd(&g_deg[eidx[EE + e]], 1);
}
__global__ void k_scan() {
    __shared__ int part[1024];
    int t = threadIdx.x;
    int base = t * 10;
    int s = 0;
    if (t < 1000)
        for (int i = 0; i < 10; i++) s += g_deg[base + i];
    part[t] = s;
    __syncthreads();
    for (int d = 1; d < 1024; d <<= 1) {
        int v = (t >= d) ? part[t - d] : 0;
        __syncthreads();
        part[t] += v;
        __syncthreads();
    }
    int excl = (t == 0) ? 0 : part[t - 1];
    if (t < 1000) {
        int run = excl;
        for (int i = 0; i < 10; i++) { g_off[base + i] = run; run += g_deg[base + i]; }
        if (t == 999) g_off[NN] = run;
    }
}
__global__ void k_fill(const int* __restrict__ eidx) {
    int e = blockIdx.x * 256 + threadIdx.x;
    if (e < EE) {
        int r = eidx[EE + e];
        int s = eidx[e];
        int pos = atomicAdd(&g_cur[r], 1);
        int slot = g_off[r] + pos;
        g_elist[slot] = e;
        g_slist[slot] = s;
    }
}

// ---------------- h = node_feats @ W_up ------------------------------------
#define H_SMEM ((128 * 128 + 32 * 128) * 4)
__global__ __launch_bounds__(256) void k_h(const float* __restrict__ feats,
                                           const float* __restrict__ Wup) {
    extern __shared__ float sm[];
    float* sW = sm;
    float* sF = sm + 16384;
    int n0 = blockIdx.x * 32;
    int t = threadIdx.x;
    for (int i = t; i < 16384; i += 256) sW[i] = Wup[i];
    for (int i = t; i < 4096; i += 256) {
        int n = n0 + (i >> 7);
        sF[i] = (n < NN) ? feats[n * CC + (i & 127)] : 0.f;
    }
    __syncthreads();
    int tk = (t & 31) * 4;
    int tn = (t >> 5) * 4;
    float acc[4][4] = {};
    for (int u = 0; u < 128; u++) {
        float4 b = *(const float4*)&sW[u * 128 + tk];
        #pragma unroll
        for (int i = 0; i < 4; i++) {
            float a = sF[(tn + i) * 128 + u];
            acc[i][0] = fmaf(a, b.x, acc[i][0]);
            acc[i][1] = fmaf(a, b.y, acc[i][1]);
            acc[i][2] = fmaf(a, b.z, acc[i][2]);
            acc[i][3] = fmaf(a, b.w, acc[i][3]);
        }
    }
    #pragma unroll
    for (int i = 0; i < 4; i++) {
        int n = n0 + tn + i;
        if (n < NN) {
            float4 v = make_float4(acc[i][0], acc[i][1], acc[i][2], acc[i][3]);
            *(float4*)&g_h[n * CC + tk] = v;
        }
    }
}

// ---------------- sc (f32x2 on k-pairs; a-loads warp-uniform) ---------------
#define SC_SMEM ((32 * 128 + 320 + 32 * 80 + 80 * 128) * 4)
__global__ __launch_bounds__(256) void k_sc(const float* __restrict__ feats,
                                            const float* __restrict__ attrs,
                                            const float* __restrict__ Wskip,
                                            float* __restrict__ sc_out) {
    extern __shared__ float sm[];
    float* sF = sm;
    float* sA = sF + 4096;
    float* sX = sA + 320;
    float* sW = sX + 2560;
    int n0 = blockIdx.x * 32;
    int t = threadIdx.x;
    for (int i = t; i < 4096; i += 256) {
        int n = n0 + (i >> 7);
        sF[i] = (n < NN) ? feats[n * CC + (i & 127)] : 0.f;
    }
    for (int i = t; i < 320; i += 256) {
        int n = n0 + i / 10;
        sA[i] = (n < NN) ? attrs[n * AA + i % 10] : 0.f;
    }
    int tk = (t & 31) * 4;
    int tn = (t >> 5) * 4;
    unsigned long long acc[4][2] = {};
    for (int uc = 0; uc < 16; uc++) {
        __syncthreads();
        for (int i = t; i < 10240; i += 256) sW[i] = Wskip[uc * 10240 + i];
        for (int idx = t; idx < 2560; idx += 256) {
            int n = idx / 80, i = idx % 80;
            sX[idx] = sF[n * 128 + uc * 8 + i / 10] * sA[n * 10 + i % 10];
        }
        __syncthreads();
        for (int i = 0; i < 80; i++) {
            ulonglong2 w = *(const ulonglong2*)&sW[i * 128 + tk];
            #pragma unroll
            for (int ii = 0; ii < 4; ii++) {
                float a = sX[(tn + ii) * 80 + i];
                unsigned long long A = pack2(a, a);
                ffma2(acc[ii][0], A, w.x);
                ffma2(acc[ii][1], A, w.y);
            }
        }
    }
    #pragma unroll
    for (int ii = 0; ii < 4; ii++) {
        int n = n0 + tn + ii;
        if (n < NN) {
            float f0, f1, f2, f3;
            unpack2(acc[ii][0], f0, f1);
            unpack2(acc[ii][1], f2, f3);
            *(float4*)&sc_out[n * CC + tk] = make_float4(f0, f1, f2, f3);
        }
    }
}

// ---------------- MLP layers 1-3 (70 KB smem, 3 CTA/SM) --------------------
#define MLP_SMEM ((512 + 4096 + 4096 + 512 + 4096 + 4096) * 4)
__global__ __launch_bounds__(256) void k_mlp123(const float* __restrict__ ef,
                                                const float* __restrict__ W1,
                                                const float* __restrict__ W2,
                                                const float* __restrict__ W3) {
    extern __shared__ float sm[];
    float* sW1 = sm;               // 512
    float* sW2 = sW1 + 512;        // 4096
    float* sW3 = sW2 + 4096;       // 4096
    float* sEF = sW3 + 4096;       // 512
    float* sTA = sEF + 512;        // 4096
    float* sTB = sTA + 4096;       // 4096
    float* sT3 = sEF;              // reuse (64*65=4160 <= 4608)
    int t = threadIdx.x;
    for (int i = t; i < 512; i += 256) sW1[i] = W1[i];
    for (int i = t; i < 4096; i += 256) sW2[i] = W2[i];
    for (int i = t; i < 4096; i += 256) sW3[i] = W3[i];
    int e0 = blockIdx.x * 64;
    for (int i = t; i < 512; i += 256) sEF[i] = ef[e0 * FF + i];
    __syncthreads();
    for (int o = t; o < 4096; o += 256) {
        int e = o >> 6, j = o & 63;
        float acc = 0.f;
        #pragma unroll
        for (int f = 0; f < 8; f++) acc = fmaf(sEF[e * 8 + f], sW1[f * 64 + j], acc);
        sTA[o] = silu(acc);
    }
    __syncthreads();
    int j0 = (t & 15) * 4, el = (t >> 4) * 4;
    {
        float acc[4][4] = {};
        for (int u = 0; u < 64; u++) {
            float4 b = *(const float4*)&sW2[u * 64 + j0];
            #pragma unroll
            for (int i = 0; i < 4; i++) {
                float a = sTA[(el + i) * 64 + u];
                acc[i][0] = fmaf(a, b.x, acc[i][0]);
                acc[i][1] = fmaf(a, b.y, acc[i][1]);
                acc[i][2] = fmaf(a, b.z, acc[i][2]);
                acc[i][3] = fmaf(a, b.w, acc[i][3]);
            }
        }
        #pragma unroll
        for (int i = 0; i < 4; i++)
            #pragma unroll
            for (int j = 0; j < 4; j++) sTB[(el + i) * 64 + j0 + j] = silu(acc[i][j]);
    }
    __syncthreads();
    {
        float acc[4][4] = {};
        for (int u = 0; u < 64; u++) {
            float4 b = *(const float4*)&sW3[u * 64 + j0];
            #pragma unroll
            for (int i = 0; i < 4; i++) {
                float a = sTB[(el + i) * 64 + u];
                acc[i][0] = fmaf(a, b.x, acc[i][0]);
                acc[i][1] = fmaf(a, b.y, acc[i][1]);
                acc[i][2] = fmaf(a, b.z, acc[i][2]);
                acc[i][3] = fmaf(a, b.w, acc[i][3]);
            }
        }
        #pragma unroll
        for (int i = 0; i < 4; i++)
            #pragma unroll
            for (int j = 0; j < 4; j++)
                sT3[(j0 + j) * 65 + el + i] = silu(acc[i][j]);
    }
    __syncthreads();
    for (int i = t; i < 4096; i += 256) {
        int u = i >> 6, e = i & 63;
        g_t3t[u * EE + e0 + e] = sT3[u * 65 + e];
    }
}

// ---------------- layer 4 GEMM: tpw = T3 @ W4 (split j-passes) -------------
// Block: 128 edges x 128 j (one pass), K=64.  256 threads, 64 KB smem -> 3 CTA/SM.
#define G4_SMEM ((8192 + 8192) * 4)
__global__ __launch_bounds__(256) void k_gemm4(const float* __restrict__ W4) {
    extern __shared__ float sm[];
    float* sW = sm;            // 64 x 128 (this pass's j slice)
    float* sA = sm + 8192;     // 64 x 128
    int t = threadIdx.x;
    int e0 = blockIdx.x * 128;
    int jp = blockIdx.y * 128;
    for (int i = t; i < 8192; i += 256) {
        int u = i >> 7, j = i & 127;
        sW[i] = W4[u * 384 + jp + j];
    }
    for (int i = t; i < 2048; i += 256) {
        int u = i >> 5, e4 = (i & 31) * 4;
        *(float4*)&sA[u * 128 + e4] = *(const float4*)&g_t3t[u * EE + e0 + e4];
    }
    __syncthreads();
    int jg = t & 15, eg = t >> 4;
    int el = eg * 8, jb = jg * 8;
    unsigned long long acc[8][4] = {};
    #pragma unroll 4
    for (int u = 0; u < 64; u++) {
        float4 a03 = *(const float4*)&sA[u * 128 + el];
        float4 a47 = *(const float4*)&sA[u * 128 + el + 4];
        ulonglong2 wA = *(const ulonglong2*)&sW[u * 128 + jb];
        ulonglong2 wB = *(const ulonglong2*)&sW[u * 128 + jb + 4];
        unsigned long long A0 = pack2(a03.x, a03.x);
        unsigned long long A1 = pack2(a03.y, a03.y);
        unsigned long long A2 = pack2(a03.z, a03.z);
        unsigned long long A3 = pack2(a03.w, a03.w);
        unsigned long long A4 = pack2(a47.x, a47.x);
        unsigned long long A5 = pack2(a47.y, a47.y);
        unsigned long long A6 = pack2(a47.z, a47.z);
        unsigned long long A7 = pack2(a47.w, a47.w);
        ffma2(acc[0][0], A0, wA.x); ffma2(acc[0][1], A0, wA.y);
        ffma2(acc[0][2], A0, wB.x); ffma2(acc[0][3], A0, wB.y);
        ffma2(acc[1][0], A1, wA.x); ffma2(acc[1][1], A1, wA.y);
        ffma2(acc[1][2], A1, wB.x); ffma2(acc[1][3], A1, wB.y);
        ffma2(acc[2][0], A2, wA.x); ffma2(acc[2][1], A2, wA.y);
        ffma2(acc[2][2], A2, wB.x); ffma2(acc[2][3], A2, wB.y);
        ffma2(acc[3][0], A3, wA.x); ffma2(acc[3][1], A3, wA.y);
        ffma2(acc[3][2], A3, wB.x); ffma2(acc[3][3], A3, wB.y);
        ffma2(acc[4][0], A4, wA.x); ffma2(acc[4][1], A4, wA.y);
        ffma2(acc[4][2], A4, wB.x); ffma2(acc[4][3], A4, wB.y);
        ffma2(acc[5][0], A5, wA.x); ffma2(acc[5][1], A5, wA.y);
        ffma2(acc[5][2], A5, wB.x); ffma2(acc[5][3], A5, wB.y);
        ffma2(acc[6][0], A6, wA.x); ffma2(acc[6][1], A6, wA.y);
        ffma2(acc[6][2], A6, wB.x); ffma2(acc[6][3], A6, wB.y);
        ffma2(acc[7][0], A7, wA.x); ffma2(acc[7][1], A7, wA.y);
        ffma2(acc[7][2], A7, wB.x); ffma2(acc[7][3], A7, wB.y);
    }
    #pragma unroll
    for (int i = 0; i < 8; i++) {
        float f0, f1, f2, f3, f4, f5, f6, f7;
        unpack2(acc[i][0], f0, f1);
        unpack2(acc[i][1], f2, f3);
        unpack2(acc[i][2], f4, f5);
        unpack2(acc[i][3], f6, f7);
        long base = (long)(e0 + el + i) * 384 + jp + jb;
        *(float4*)&g_tpw[base]     = make_float4(f0, f1, f2, f3);
        *(float4*)&g_tpw[base + 4] = make_float4(f4, f5, f6, f7);
    }
}

// ---------------- gather conv_tp + segment_sum -----------------------------
__global__ __launch_bounds__(256) void k_gather(const float* __restrict__ yr,
                                                const float* __restrict__ yi) {
    int t = threadIdx.x;
    int n = blockIdx.x * 8 + (t >> 5);
    int c0 = (t & 31) * 4;
    float4 ar[9], ai[9];
    #pragma unroll
    for (int m = 0; m < 9; m++) {
        ar[m] = make_float4(0.f, 0.f, 0.f, 0.f);
        ai[m] = make_float4(0.f, 0.f, 0.f, 0.f);
    }
    int beg = g_off[n], end = g_off[n + 1];
    #pragma unroll 2
    for (int i = beg; i < end; i++) {
        int e = g_elist[i];
        int s = g_slist[i];
        float4 x  = *(const float4*)&g_h[s * CC + c0];
        const float* tw = g_tpw + (long)e * 384;
        float4 t0 = *(const float4*)&tw[c0];
        float4 t1 = *(const float4*)&tw[128 + c0];
        float4 t2 = *(const float4*)&tw[256 + c0];
        float4 xw0 = make_float4(x.x * t0.x, x.y * t0.y, x.z * t0.z, x.w * t0.w);
        float4 xw1 = make_float4(x.x * t1.x, x.y * t1.y, x.z * t1.z, x.w * t1.w);
        float4 xw2 = make_float4(x.x * t2.x, x.y * t2.y, x.z * t2.z, x.w * t2.w);
        const float* yre = yr + e * 9;
        const float* yie = yi + e * 9;
        #pragma unroll
        for (int m = 0; m < 9; m++) {
            float4 xw = (m == 0) ? xw0 : (m < 4) ? xw1 : xw2;
            float vr = yre[m], vi = yie[m];
            ar[m].x = fmaf(xw.x, vr, ar[m].x); ar[m].y = fmaf(xw.y, vr, ar[m].y);
            ar[m].z = fmaf(xw.z, vr, ar[m].z); ar[m].w = fmaf(xw.w, vr, ar[m].w);
            ai[m].x = fmaf(xw.x, vi, ai[m].x); ai[m].y = fmaf(xw.y, vi, ai[m].y);
            ai[m].z = fmaf(xw.z, vi, ai[m].z); ai[m].w = fmaf(xw.w, vi, ai[m].w);
        }
    }
    float* mr = g_msg_r + n * MSGW;
    float* mi = g_msg_i + n * MSGW;
    *(float4*)&mr[c0] = ar[0];
    *(float4*)&mi[c0] = ai[0];
    #pragma unroll
    for (int m = 0; m < 3; m++) {
        *(float4*)&mr[128 + m * 128 + c0] = ar[1 + m];
        *(float4*)&mi[128 + m * 128 + c0] = ai[1 + m];
    }
    #pragma unroll
    for (int m = 0; m < 5; m++) {
        *(float4*)&mr[512 + m * 128 + c0] = ar[4 + m];
        *(float4*)&mi[512 + m * 128 + c0] = ai[4 + m];
    }
}

// ---------------- linear_irreps (persistent, fused r+i, f32x2) -------------
#define LIN_SMEM ((128 * 128 + 2 * 32 * 128) * 4)
__global__ __launch_bounds__(256) void k_linear(const float* __restrict__ W,
                                                float* __restrict__ out_r,
                                                float* __restrict__ out_i,
                                                int d, int loff, int moff) {
    extern __shared__ float sm[];
    float* sW  = sm;
    float* sAr = sm + 16384;
    float* sAi = sAr + 4096;
    int nrows = NN * d;
    int t = threadIdx.x;
    for (int i = t; i < 16384; i += 256) sW[i] = W[i];
    int tk = (t & 31) * 4;
    int tr = (t >> 5) * 4;
    for (int r0 = blockIdx.x * 32; r0 < nrows; r0 += gridDim.x * 32) {
        __syncthreads();
        for (int i = t; i < 4096; i += 256) {
            int rl = i >> 7, u = i & 127;
            int row = r0 + rl;
            float vr = 0.f, vi = 0.f;
            if (row < nrows) {
                int n = row / d, m = row % d;
                int off = n * MSGW + loff + m * 128 + u;
                vr = g_msg_r[off];
                vi = g_msg_i[off];
            }
            sAr[i] = vr;
            sAi[i] = vi;
        }
        __syncthreads();
        unsigned long long accr[4][2] = {};
        unsigned long long acci[4][2] = {};
        for (int u = 0; u < 128; u++) {
            ulonglong2 w = *(const ulonglong2*)&sW[u * 128 + tk];
            #pragma unroll
            for (int i = 0; i < 4; i++) {
                float a = sAr[(tr + i) * 128 + u];
                unsigned long long A = pack2(a, a);
                ffma2(accr[i][0], A, w.x);
                ffma2(accr[i][1], A, w.y);
                float c = sAi[(tr + i) * 128 + u];
                unsigned long long Cc = pack2(c, c);
                ffma2(acci[i][0], Cc, w.x);
                ffma2(acci[i][1], Cc, w.y);
            }
        }
        #pragma unroll
        for (int i = 0; i < 4; i++) {
            int row = r0 + tr + i;
            if (row < nrows) {
                int n = row / d, m = row % d;
                float* orp = out_r + n * MSGW + moff + m;
                float* oip = out_i + n * MSGW + moff + m;
                float r01[4], i01[4];
                unpack2(accr[i][0], r01[0], r01[1]);
                unpack2(accr[i][1], r01[2], r01[3]);
                unpack2(acci[i][0], i01[0], i01[1]);
                unpack2(acci[i][1], i01[2], i01[3]);
                #pragma unroll
                for (int j = 0; j < 4; j++) {
                    orp[(tk + j) * 9] = r01[j];
                    oip[(tk + j) * 9] = i01[j];
                }
            }
        }
    }
}

// ---------------- launch ---------------------------------------------------
extern "C" void kernel_launch(void* const* d_in, const int* in_sizes, int n_in,
                              void* d_out, int out_size) {
    const float* node_attrs = (const float*)d_in[0];
    const float* node_feats = (const float*)d_in[1];
    const float* yr        = (const float*)d_in[2];
    const float* yi        = (const float*)d_in[3];
    const float* ef        = (const float*)d_in[4];
    const int*   eidx      = (const int*)  d_in[5];
    const float* Wup       = (const float*)d_in[6];
    const float* Wskip     = (const float*)d_in[7];
    const float* W1        = (const float*)d_in[8];
    const float* W2        = (const float*)d_in[9];
    const float* W3        = (const float*)d_in[10];
    const float* W4        = (const float*)d_in[11];
    const float* Wl0       = (const float*)d_in[12];
    const float* Wl1       = (const float*)d_in[13];
    const float* Wl2       = (const float*)d_in[14];

    float* out   = (float*)d_out;
    float* out_r = out;
    float* out_i = out + OUTR_ELEMS;
    float* out_s = out + 2 * OUTR_ELEMS;

    cudaFuncSetAttribute(k_h,      cudaFuncAttributeMaxDynamicSharedMemorySize, H_SMEM);
    cudaFuncSetAttribute(k_sc,     cudaFuncAttributeMaxDynamicSharedMemorySize, SC_SMEM);
    cudaFuncSetAttribute(k_mlp123, cudaFuncAttributeMaxDynamicSharedMemorySize, MLP_SMEM);
    cudaFuncSetAttribute(k_gemm4,  cudaFuncAttributeMaxDynamicSharedMemorySize, G4_SMEM);
    cudaFuncSetAttribute(k_linear, cudaFuncAttributeMaxDynamicSharedMemorySize, LIN_SMEM);

    // idx 0..2
    k_mlp123<<<EE / 64, 256, MLP_SMEM>>>(ef, W1, W2, W3);
    k_reset<<<(NN + 255) / 256, 256>>>();
    k_count<<<(EE + 255) / 256, 256>>>(eidx);
    // idx 3: profiled launch
    k_gemm4<<<dim3(EE / 128, 3), 256, G4_SMEM>>>(W4);
    // idx 4..7
    k_scan<<<1, 1024>>>();
    k_fill<<<(EE + 255) / 256, 256>>>(eidx);
    k_h<<<(NN + 31) / 32, 256, H_SMEM>>>(node_feats, Wup);
    k_sc<<<(NN + 31) / 32, 256, SC_SMEM>>>(node_feats, node_attrs, Wskip, out_s);
    // idx 8
    k_gather<<<NN / 8, 256>>>(yr, yi);
    // idx 9..11
    k_linear<<<296, 256, LIN_SMEM>>>(Wl0, out_r, out_i, 1, 0,   0);
    k_linear<<<296, 256, LIN_SMEM>>>(Wl1, out_r, out_i, 3, 128, 1);
    k_linear<<<296, 256, LIN_SMEM>>>(Wl2, out_r, out_i, 5, 512, 4);
}